// round 7
// baseline (speedup 1.0000x reference)
#include <cuda_runtime.h>
#include <cstdint>

// Embedding gather: out[i] = table[ids_flat[i]], D = 64 fp32 (256B/row).
// - 16 threads per row-chunk, one float4 per thread.
// - 4 independent gathers per thread (quarters of the index space),
//   front-batched: 4 id LDGs -> 4 table LDG.128s in flight -> 4 streaming
//   stores. MLP_p1=4 measured sweet spot (8 overflows L1tex wavefront queue).
// - __stcs output stores keep the table L2-resident (repeat ids hit L2).
// - 1024-thread blocks: fewest resident CTAs/SM at equal warp count ->
//   lowest cross-CTA L1tex queue contention.
// - Pure 32-bit index math (total chunks 13.1M, id*16+chunk < 16M) to
//   shorten the address-gen chain feeding each gather LDG.

__global__ void __launch_bounds__(1024)
embed_gather_kernel(const int* __restrict__ ids,
                    const float4* __restrict__ table4,   // [VOCAB, 16] float4
                    float4* __restrict__ out4,           // [N, 16] float4
                    unsigned total, unsigned vocab)
{
    unsigned q = total >> 2;                             // n_rows % 4 == 0 here
    unsigned g = blockIdx.x * blockDim.x + threadIdx.x;

    if (g < q) {
        unsigned g0 = g, g1 = g + q, g2 = g + 2u * q, g3 = g + 3u * q;

        // Batch id loads (4 independent LDGs, broadcast within half-warp).
        int id0 = __ldg(&ids[g0 >> 4]);
        int id1 = __ldg(&ids[g1 >> 4]);
        int id2 = __ldg(&ids[g2 >> 4]);
        int id3 = __ldg(&ids[g3 >> 4]);
        if ((unsigned)id0 >= vocab) id0 = 0;
        if ((unsigned)id1 >= vocab) id1 = 0;
        if ((unsigned)id2 >= vocab) id2 = 0;
        if ((unsigned)id3 >= vocab) id3 = 0;

        // 4 independent gathers in flight (32-bit element offsets).
        float4 v0 = __ldg(table4 + (((unsigned)id0 << 4) | (g0 & 15u)));
        float4 v1 = __ldg(table4 + (((unsigned)id1 << 4) | (g1 & 15u)));
        float4 v2 = __ldg(table4 + (((unsigned)id2 << 4) | (g2 & 15u)));
        float4 v3 = __ldg(table4 + (((unsigned)id3 << 4) | (g3 & 15u)));

        __stcs(out4 + g0, v0);      // streaming store: don't pollute L2
        __stcs(out4 + g1, v1);
        __stcs(out4 + g2, v2);
        __stcs(out4 + g3, v3);
    } else {
        // Tail for totals not divisible by 4 (not hit with these shapes).
        unsigned rem = 4u * q + (g - q);
        if (rem < total) {
            int id = __ldg(&ids[rem >> 4]);
            if ((unsigned)id >= vocab) id = 0;
            __stcs(out4 + rem,
                   __ldg(table4 + (((unsigned)id << 4) | (rem & 15u))));
        }
    }
}

extern "C" void kernel_launch(void* const* d_in, const int* in_sizes, int n_in,
                              void* d_out, int out_size)
{
    const int*    ids   = (const int*)d_in[0];
    const float4* table = (const float4*)d_in[1];
    float4*       out   = (float4*)d_out;

    unsigned n_rows = (unsigned)in_sizes[0];             // 819200
    unsigned vocab  = (unsigned)(in_sizes[1] / 64);      // 1,000,000

    unsigned total4   = n_rows * 16u;                    // 13,107,200
    unsigned q        = total4 >> 2;
    unsigned tail     = total4 - 4u * q;                 // 0..3
    unsigned nthreads = q + tail;

    unsigned threads = 1024;
    unsigned blocks  = (nthreads + threads - 1u) / threads;
    embed_gather_kernel<<<blocks, threads>>>(ids, table, out, total4, vocab);
}

// round 8
// speedup vs baseline: 1.0035x; 1.0035x over previous
#include <cuda_runtime.h>
#include <cstdint>

// Embedding gather: out[i] = table[ids_flat[i]], D = 64 fp32 (256B/row).
// Final config from the sweep:
// - 16 threads per row-chunk, one float4 per thread.
// - 4 independent gathers per thread (quarters of the index space),
//   front-batched: 4 id LDGs -> 4 table LDG.128s in flight -> 4 streaming
//   stores. MLP sweep: {2:65.6, 4:63.4(best), 8:65.5} us.
// - __stcs output stores keep the table L2-resident (repeat ids hit L2);
//   measured traffic sits at the compulsory floor (~335MB).
// - Block sweep: {256:63.6, 512:63.4(best), 1024:63.7} us.
// - Pure 32-bit index math (total chunks 13.1M, id*16+chunk < 16M):
//   shortest address-gen chain feeding each gather LDG (alu 13%->5%).

__global__ void __launch_bounds__(512)
embed_gather_kernel(const int* __restrict__ ids,
                    const float4* __restrict__ table4,   // [VOCAB, 16] float4
                    float4* __restrict__ out4,           // [N, 16] float4
                    unsigned total, unsigned vocab)
{
    unsigned q = total >> 2;                             // n_rows % 4 == 0 here
    unsigned g = blockIdx.x * blockDim.x + threadIdx.x;

    if (g < q) {
        unsigned g0 = g, g1 = g + q, g2 = g + 2u * q, g3 = g + 3u * q;

        // Batch id loads (4 independent LDGs, broadcast within half-warp).
        int id0 = __ldg(&ids[g0 >> 4]);
        int id1 = __ldg(&ids[g1 >> 4]);
        int id2 = __ldg(&ids[g2 >> 4]);
        int id3 = __ldg(&ids[g3 >> 4]);
        if ((unsigned)id0 >= vocab) id0 = 0;
        if ((unsigned)id1 >= vocab) id1 = 0;
        if ((unsigned)id2 >= vocab) id2 = 0;
        if ((unsigned)id3 >= vocab) id3 = 0;

        // 4 independent gathers in flight (32-bit element offsets).
        float4 v0 = __ldg(table4 + (((unsigned)id0 << 4) | (g0 & 15u)));
        float4 v1 = __ldg(table4 + (((unsigned)id1 << 4) | (g1 & 15u)));
        float4 v2 = __ldg(table4 + (((unsigned)id2 << 4) | (g2 & 15u)));
        float4 v3 = __ldg(table4 + (((unsigned)id3 << 4) | (g3 & 15u)));

        __stcs(out4 + g0, v0);      // streaming store: don't pollute L2
        __stcs(out4 + g1, v1);
        __stcs(out4 + g2, v2);
        __stcs(out4 + g3, v3);
    } else {
        // Tail for totals not divisible by 4 (not hit with these shapes).
        unsigned rem = 4u * q + (g - q);
        if (rem < total) {
            int id = __ldg(&ids[rem >> 4]);
            if ((unsigned)id >= vocab) id = 0;
            __stcs(out4 + rem,
                   __ldg(table4 + (((unsigned)id << 4) | (rem & 15u))));
        }
    }
}

extern "C" void kernel_launch(void* const* d_in, const int* in_sizes, int n_in,
                              void* d_out, int out_size)
{
    const int*    ids   = (const int*)d_in[0];
    const float4* table = (const float4*)d_in[1];
    float4*       out   = (float4*)d_out;

    unsigned n_rows = (unsigned)in_sizes[0];             // 819200
    unsigned vocab  = (unsigned)(in_sizes[1] / 64);      // 1,000,000

    unsigned total4   = n_rows * 16u;                    // 13,107,200
    unsigned q        = total4 >> 2;
    unsigned tail     = total4 - 4u * q;                 // 0..3
    unsigned nthreads = q + tail;

    unsigned threads = 512;
    unsigned blocks  = (nthreads + threads - 1u) / threads;
    embed_gather_kernel<<<blocks, threads>>>(ids, table, out, total4, vocab);
}